// round 14
// baseline (speedup 1.0000x reference)
#include <cuda_runtime.h>
#include <math.h>

#define CC 32
#define HH 256
#define WW 256
#define HWN (HH * WW)
#define KP 9
#define SEGO 62                 // output pixels per warp
#define NWPB 1058               // warps per batch = ceil(HWN/SEGO)
#define NBATCH 4
#define NWTOT (NWPB * NBATCH)   // 4232
#define NT 32                   // ONE warp per block
#define HW HWN

__device__ __forceinline__ float2 ld2(const float* p) {
    return *reinterpret_cast<const float2*>(p);
}

__device__ __forceinline__ void weights9(const float* __restrict__ dot,
                                         const float* __restrict__ pn2,
                                         float fn2,
                                         float* __restrict__ wgt)
{
    float rfn = rsqrtf(fmaxf(fn2, 1e-24f));
    float cs[KP], ed[KP];
    float csum = 0.0f, esum = 0.0f;
#pragma unroll
    for (int k = 0; k < KP; k++) {
        float rp = rsqrtf(fmaxf(pn2[k], 1e-24f));
        float cv = dot[k] * rp * rfn;
        float d2 = fmaxf(fmaf(-2.0f, dot[k], pn2[k] + fn2), 0.0f);
        float sd = d2 * rsqrtf(fmaxf(d2, 1e-30f));   // ~= sqrt(d2), 0-safe
        cs[k] = __expf(cv);
        csum += cs[k];
        ed[k] = __expf(-sd);
        esum += ed[k];
    }
    float ci = __fdividef(0.5f, csum);
    float ei = __fdividef(0.5f, esum);
#pragma unroll
    for (int k = 0; k < KP; k++) wgt[k] = cs[k] * ci + ed[k] * ei;
}

// MODE 0: clean interior. MODE 1: row-wrap inside window. MODE 2: y/range edge.
template<int MODE>
__device__ __forceinline__ void body(
    int lane, int n0, int b,
    const float* __restrict__ fe,
    const float* __restrict__ fu,
    float* __restrict__ out)
{
    const unsigned FULL = 0xffffffffu;
    const int nA = n0 + 2 * lane;
    const int nB = nA + 1;

    int ca = nA;
    if (MODE == 2) ca = min(max(nA, 0), HWN - 2);

    float ml = 1.0f, mr = 1.0f;
    if (MODE >= 1) {
        ml = ((ca & 255) != 0) ? 1.0f : 0.0f;
        mr = (((ca + 2) & 255) != 0) ? 1.0f : 0.0f;
    }

    float mtA = 1.0f, mtB = 1.0f, mmA = 1.0f, mmB = 1.0f, mbA = 1.0f, mbB = 1.0f;
    int ot = -WW, obo = WW;
    if (MODE == 2) {
        mmA = (nA >= 0 && nA < HWN) ? 1.0f : 0.0f;
        mmB = (nB >= 0 && nB < HWN) ? 1.0f : 0.0f;
        mtA = (nA >= WW && nA < HWN) ? 1.0f : 0.0f;
        mtB = (nB >= WW && nB < HWN) ? 1.0f : 0.0f;
        mbA = (nA >= 0 && nA + WW < HWN) ? 1.0f : 0.0f;
        mbB = (nB >= 0 && nB + WW < HWN) ? 1.0f : 0.0f;
        ot  = (nA >= WW) ? -WW : 0;
        obo = (nA + 1 + WW < HWN) ? WW : 0;
    }

    const size_t base = ((size_t)b * CC) * HW + ca;
    const float* fup = fu + base;
    const float* fep = fe + base;

    // ---- pass 1: per-column scatter accumulators ----
    float uA[3] = {0,0,0}, mA[3] = {0,0,0}, wA[3] = {0,0,0}, qA[3] = {0,0,0};
    float uB[3] = {0,0,0}, mB[3] = {0,0,0}, wB[3] = {0,0,0}, qB[3] = {0,0,0};
    float fnA = 0.0f, fnB = 0.0f;

#pragma unroll 8
    for (int c = 0; c < CC; c++) {
        const float* p = fup + c * HW;
        float2 vt = ld2(p + ot);
        float2 vm = ld2(p);
        float2 vb = ld2(p + obo);
        float2 f  = ld2(fep + c * HW);
        if (MODE == 2) {
            vt.x *= mtA; vt.y *= mtB;
            vm.x *= mmA; vm.y *= mmB;
            vb.x *= mbA; vb.y *= mbB;
            f.x  *= mmA; f.y  *= mmB;
        }

        float fl = __shfl_up_sync(FULL, f.y, 1);    // f(cA-1)
        float fr = __shfl_down_sync(FULL, f.x, 1);  // f(cB+1)
        if (MODE >= 1) { fl *= ml; fr *= mr; }

        fnA = fmaf(f.x, f.x, fnA);
        fnB = fmaf(f.y, f.y, fnB);

        float vx, vy;
        vx = vt.x; vy = vt.y;
        uA[0] = fmaf(vx, f.y, uA[0]); mA[0] = fmaf(vx, f.x, mA[0]);
        wA[0] = fmaf(vx, fl,  wA[0]); qA[0] = fmaf(vx, vx,  qA[0]);
        uB[0] = fmaf(vy, fr,  uB[0]); mB[0] = fmaf(vy, f.y, mB[0]);
        wB[0] = fmaf(vy, f.x, wB[0]); qB[0] = fmaf(vy, vy,  qB[0]);
        vx = vm.x; vy = vm.y;
        uA[1] = fmaf(vx, f.y, uA[1]); mA[1] = fmaf(vx, f.x, mA[1]);
        wA[1] = fmaf(vx, fl,  wA[1]); qA[1] = fmaf(vx, vx,  qA[1]);
        uB[1] = fmaf(vy, fr,  uB[1]); mB[1] = fmaf(vy, f.y, mB[1]);
        wB[1] = fmaf(vy, f.x, wB[1]); qB[1] = fmaf(vy, vy,  qB[1]);
        vx = vb.x; vy = vb.y;
        uA[2] = fmaf(vx, f.y, uA[2]); mA[2] = fmaf(vx, f.x, mA[2]);
        wA[2] = fmaf(vx, fl,  wA[2]); qA[2] = fmaf(vx, vx,  qA[2]);
        uB[2] = fmaf(vy, fr,  uB[2]); mB[2] = fmaf(vy, f.y, mB[2]);
        wB[2] = fmaf(vy, f.x, wB[2]); qB[2] = fmaf(vy, vy,  qB[2]);
    }

    // ---- redistribute + softmax ----
    float wgtA[KP], wgtB[KP];
    {
        float dot[KP], pn2[KP];
#pragma unroll
        for (int d = 0; d < 3; d++) {
            float a0 = __shfl_up_sync(FULL, uB[d], 1);
            float q0 = __shfl_up_sync(FULL, qB[d], 1);
            if (MODE >= 1) { a0 *= ml; q0 *= ml; }
            dot[d*3 + 0] = a0;
            dot[d*3 + 1] = mA[d];
            dot[d*3 + 2] = wB[d];
            pn2[d*3 + 0] = q0;
            pn2[d*3 + 1] = qA[d];
            pn2[d*3 + 2] = qB[d];
        }
        weights9(dot, pn2, fnA, wgtA);
    }
    {
        float dot[KP], pn2[KP];
#pragma unroll
        for (int d = 0; d < 3; d++) {
            float a2 = __shfl_down_sync(FULL, wA[d], 1);
            float q2 = __shfl_down_sync(FULL, qA[d], 1);
            if (MODE >= 1) { a2 *= mr; q2 *= mr; }
            dot[d*3 + 0] = uA[d];
            dot[d*3 + 1] = mB[d];
            dot[d*3 + 2] = a2;
            pn2[d*3 + 0] = qA[d];
            pn2[d*3 + 1] = qB[d];
            pn2[d*3 + 2] = q2;
        }
        weights9(dot, pn2, fnB, wgtB);
    }

    // pre-shuffled neighbor weights (link-masked)
    float wlB0 = __shfl_up_sync(FULL, wgtB[2], 1);
    float wlB1 = __shfl_up_sync(FULL, wgtB[5], 1);
    float wlB2 = __shfl_up_sync(FULL, wgtB[8], 1);
    float wrA0 = __shfl_down_sync(FULL, wgtA[0], 1);
    float wrA1 = __shfl_down_sync(FULL, wgtA[3], 1);
    float wrA2 = __shfl_down_sync(FULL, wgtA[6], 1);
    if (MODE >= 1) {
        wlB0 *= ml; wlB1 *= ml; wlB2 *= ml;
        wrA0 *= mr; wrA1 *= mr; wrA2 *= mr;
    }

    bool st0 = (lane >= 1);
    bool st1 = (lane <= 30);
    if (MODE == 2) {
        st0 = st0 && (nA >= 0) && (nA < HWN);
        st1 = st1 && (nB >= 0) && (nB < HWN);
    }
    float* ob = out + base;

    // ---- pass 2 (reverse channel order: last pass-1 channels are L1-hot) ----
#pragma unroll 8
    for (int ci = 0; ci < CC; ci++) {
        const int c = CC - 1 - ci;
        const float* p = fup + c * HW;
        float2 vt = ld2(p + ot);
        float2 vm = ld2(p);
        float2 vb = ld2(p + obo);
        float2 f  = ld2(fep + c * HW);
        if (MODE == 2) {
            vt.x *= mtA; vt.y *= mtB;
            vm.x *= mmA; vm.y *= mmB;
            vb.x *= mbA; vb.y *= mbB;
        }

        float accA = vt.x * wgtA[1];
        accA = fmaf(vm.x, wgtA[4], accA);
        accA = fmaf(vb.x, wgtA[7], accA);
        accA = fmaf(vt.y, wgtA[2], accA);
        accA = fmaf(vm.y, wgtA[5], accA);
        accA = fmaf(vb.y, wgtA[8], accA);
        float accB = vt.y * wgtB[1];
        accB = fmaf(vm.y, wgtB[4], accB);
        accB = fmaf(vb.y, wgtB[7], accB);
        accB = fmaf(vt.x, wgtB[0], accB);
        accB = fmaf(vm.x, wgtB[3], accB);
        accB = fmaf(vb.x, wgtB[6], accB);
        float cl = vt.x * wlB0;
        cl = fmaf(vm.x, wlB1, cl);
        cl = fmaf(vb.x, wlB2, cl);
        float cr = vt.y * wrA0;
        cr = fmaf(vm.y, wrA1, cr);
        cr = fmaf(vb.y, wrA2, cr);

        float fromR = __shfl_down_sync(FULL, cl, 1);
        float fromL = __shfl_up_sync(FULL, cr, 1);

        float oA = accA + fromL + f.x;
        float oB = accB + fromR + f.y;

        float* q = ob + c * HW;
        if (st0 && st1) {
            *reinterpret_cast<float2*>(q) = make_float2(oA, oB);
        } else {
            if (st0) q[0] = oA;
            if (st1) q[1] = oB;
        }
    }
}

__global__ __launch_bounds__(NT, 28) void asfr_kernel(
    const float* __restrict__ fe,
    const float* __restrict__ fu,
    float* __restrict__ out)
{
    const int lane = threadIdx.x & 31;
    const int G    = blockIdx.x;         // one warp per block
    const int b    = G / NWPB;
    const int W    = G - b * NWPB;
    const int n0   = W * SEGO - 2;

    if (W <= 4 || W >= 1052)
        body<2>(lane, n0, b, fe, fu, out);
    else if ((n0 & 255) >= 193)
        body<1>(lane, n0, b, fe, fu, out);
    else
        body<0>(lane, n0, b, fe, fu, out);
}

extern "C" void kernel_launch(void* const* d_in, const int* in_sizes, int n_in,
                              void* d_out, int out_size)
{
    (void)in_sizes; (void)n_in; (void)out_size;
    const float* fe = (const float*)d_in[0];
    const float* fu = (const float*)d_in[1];
    float* out = (float*)d_out;

    asfr_kernel<<<NWTOT, NT>>>(fe, fu, out);   // 4232 one-warp blocks
}

// round 15
// speedup vs baseline: 1.0015x; 1.0015x over previous
#include <cuda_runtime.h>
#include <math.h>

#define CC 32
#define HH 256
#define WW 256
#define HWN (HH * WW)
#define KP 9
#define SEGO 62                 // output pixels per warp
#define NWPB 1058               // warps per batch = ceil(HWN/SEGO)
#define NBATCH 4
#define NWTOT (NWPB * NBATCH)   // 4232
#define NT 32                   // ONE warp per block
#define HW HWN

__device__ __forceinline__ float2 ld2(const float* p) {
    return *reinterpret_cast<const float2*>(p);
}

__device__ __forceinline__ void weights9(const float* __restrict__ dot,
                                         const float* __restrict__ pn2,
                                         float fn2,
                                         float* __restrict__ wgt)
{
    float rfn = rsqrtf(fmaxf(fn2, 1e-24f));
    float cs[KP], ed[KP];
    float csum = 0.0f, esum = 0.0f;
#pragma unroll
    for (int k = 0; k < KP; k++) {
        float rp = rsqrtf(fmaxf(pn2[k], 1e-24f));
        float cv = dot[k] * rp * rfn;
        float d2 = fmaxf(fmaf(-2.0f, dot[k], pn2[k] + fn2), 0.0f);
        float sd = d2 * rsqrtf(fmaxf(d2, 1e-30f));   // ~= sqrt(d2), 0-safe
        cs[k] = __expf(cv);
        csum += cs[k];
        ed[k] = __expf(-sd);
        esum += ed[k];
    }
    float ci = __fdividef(0.5f, csum);
    float ei = __fdividef(0.5f, esum);
#pragma unroll
    for (int k = 0; k < KP; k++) wgt[k] = cs[k] * ci + ed[k] * ei;
}

// MODE 0: clean interior. MODE 1: row-wrap inside window. MODE 2: y/range edge.
template<int MODE>
__device__ __forceinline__ void body(
    int lane, int n0, int b,
    const float* __restrict__ fe,
    const float* __restrict__ fu,
    float* __restrict__ out)
{
    const unsigned FULL = 0xffffffffu;
    const int nA = n0 + 2 * lane;
    const int nB = nA + 1;

    int ca = nA;
    if (MODE == 2) ca = min(max(nA, 0), HWN - 2);

    float ml = 1.0f, mr = 1.0f;
    if (MODE >= 1) {
        ml = ((ca & 255) != 0) ? 1.0f : 0.0f;
        mr = (((ca + 2) & 255) != 0) ? 1.0f : 0.0f;
    }

    float mtA = 1.0f, mtB = 1.0f, mmA = 1.0f, mmB = 1.0f, mbA = 1.0f, mbB = 1.0f;
    int ot = -WW, obo = WW;
    if (MODE == 2) {
        mmA = (nA >= 0 && nA < HWN) ? 1.0f : 0.0f;
        mmB = (nB >= 0 && nB < HWN) ? 1.0f : 0.0f;
        mtA = (nA >= WW && nA < HWN) ? 1.0f : 0.0f;
        mtB = (nB >= WW && nB < HWN) ? 1.0f : 0.0f;
        mbA = (nA >= 0 && nA + WW < HWN) ? 1.0f : 0.0f;
        mbB = (nB >= 0 && nB + WW < HWN) ? 1.0f : 0.0f;
        ot  = (nA >= WW) ? -WW : 0;
        obo = (nA + 1 + WW < HWN) ? WW : 0;
    }

    const size_t base = ((size_t)b * CC) * HW + ca;
    const float* fup = fu + base;
    const float* fep = fe + base;

    // ---- pass 1: per-column scatter accumulators ----
    float uA[3] = {0,0,0}, mA[3] = {0,0,0}, wA[3] = {0,0,0}, qA[3] = {0,0,0};
    float uB[3] = {0,0,0}, mB[3] = {0,0,0}, wB[3] = {0,0,0}, qB[3] = {0,0,0};
    float fnA = 0.0f, fnB = 0.0f;

#pragma unroll 4
    for (int c = 0; c < CC; c++) {
        const float* p = fup + c * HW;
        float2 vt = ld2(p + ot);
        float2 vm = ld2(p);
        float2 vb = ld2(p + obo);
        float2 f  = ld2(fep + c * HW);
        if (MODE == 2) {
            vt.x *= mtA; vt.y *= mtB;
            vm.x *= mmA; vm.y *= mmB;
            vb.x *= mbA; vb.y *= mbB;
            f.x  *= mmA; f.y  *= mmB;
        }

        float fl = __shfl_up_sync(FULL, f.y, 1);    // f(cA-1)
        float fr = __shfl_down_sync(FULL, f.x, 1);  // f(cB+1)
        if (MODE >= 1) { fl *= ml; fr *= mr; }

        fnA = fmaf(f.x, f.x, fnA);
        fnB = fmaf(f.y, f.y, fnB);

        float vx, vy;
        vx = vt.x; vy = vt.y;
        uA[0] = fmaf(vx, f.y, uA[0]); mA[0] = fmaf(vx, f.x, mA[0]);
        wA[0] = fmaf(vx, fl,  wA[0]); qA[0] = fmaf(vx, vx,  qA[0]);
        uB[0] = fmaf(vy, fr,  uB[0]); mB[0] = fmaf(vy, f.y, mB[0]);
        wB[0] = fmaf(vy, f.x, wB[0]); qB[0] = fmaf(vy, vy,  qB[0]);
        vx = vm.x; vy = vm.y;
        uA[1] = fmaf(vx, f.y, uA[1]); mA[1] = fmaf(vx, f.x, mA[1]);
        wA[1] = fmaf(vx, fl,  wA[1]); qA[1] = fmaf(vx, vx,  qA[1]);
        uB[1] = fmaf(vy, fr,  uB[1]); mB[1] = fmaf(vy, f.y, mB[1]);
        wB[1] = fmaf(vy, f.x, wB[1]); qB[1] = fmaf(vy, vy,  qB[1]);
        vx = vb.x; vy = vb.y;
        uA[2] = fmaf(vx, f.y, uA[2]); mA[2] = fmaf(vx, f.x, mA[2]);
        wA[2] = fmaf(vx, fl,  wA[2]); qA[2] = fmaf(vx, vx,  qA[2]);
        uB[2] = fmaf(vy, fr,  uB[2]); mB[2] = fmaf(vy, f.y, mB[2]);
        wB[2] = fmaf(vy, f.x, wB[2]); qB[2] = fmaf(vy, vy,  qB[2]);
    }

    // ---- redistribute + softmax ----
    float wgtA[KP], wgtB[KP];
    {
        float dot[KP], pn2[KP];
#pragma unroll
        for (int d = 0; d < 3; d++) {
            float a0 = __shfl_up_sync(FULL, uB[d], 1);
            float q0 = __shfl_up_sync(FULL, qB[d], 1);
            if (MODE >= 1) { a0 *= ml; q0 *= ml; }
            dot[d*3 + 0] = a0;
            dot[d*3 + 1] = mA[d];
            dot[d*3 + 2] = wB[d];
            pn2[d*3 + 0] = q0;
            pn2[d*3 + 1] = qA[d];
            pn2[d*3 + 2] = qB[d];
        }
        weights9(dot, pn2, fnA, wgtA);
    }
    {
        float dot[KP], pn2[KP];
#pragma unroll
        for (int d = 0; d < 3; d++) {
            float a2 = __shfl_down_sync(FULL, wA[d], 1);
            float q2 = __shfl_down_sync(FULL, qA[d], 1);
            if (MODE >= 1) { a2 *= mr; q2 *= mr; }
            dot[d*3 + 0] = uA[d];
            dot[d*3 + 1] = mB[d];
            dot[d*3 + 2] = a2;
            pn2[d*3 + 0] = qA[d];
            pn2[d*3 + 1] = qB[d];
            pn2[d*3 + 2] = q2;
        }
        weights9(dot, pn2, fnB, wgtB);
    }

    // pre-shuffled neighbor weights (link-masked)
    float wlB0 = __shfl_up_sync(FULL, wgtB[2], 1);
    float wlB1 = __shfl_up_sync(FULL, wgtB[5], 1);
    float wlB2 = __shfl_up_sync(FULL, wgtB[8], 1);
    float wrA0 = __shfl_down_sync(FULL, wgtA[0], 1);
    float wrA1 = __shfl_down_sync(FULL, wgtA[3], 1);
    float wrA2 = __shfl_down_sync(FULL, wgtA[6], 1);
    if (MODE >= 1) {
        wlB0 *= ml; wlB1 *= ml; wlB2 *= ml;
        wrA0 *= mr; wrA1 *= mr; wrA2 *= mr;
    }

    bool st0 = (lane >= 1);
    bool st1 = (lane <= 30);
    if (MODE == 2) {
        st0 = st0 && (nA >= 0) && (nA < HWN);
        st1 = st1 && (nB >= 0) && (nB < HWN);
    }
    float* ob = out + base;

    // ---- pass 2 (reverse channel order: last pass-1 channels are L1-hot) ----
#pragma unroll 4
    for (int ci = 0; ci < CC; ci++) {
        const int c = CC - 1 - ci;
        const float* p = fup + c * HW;
        float2 vt = ld2(p + ot);
        float2 vm = ld2(p);
        float2 vb = ld2(p + obo);
        float2 f  = ld2(fep + c * HW);
        if (MODE == 2) {
            vt.x *= mtA; vt.y *= mtB;
            vm.x *= mmA; vm.y *= mmB;
            vb.x *= mbA; vb.y *= mbB;
        }

        float accA = vt.x * wgtA[1];
        accA = fmaf(vm.x, wgtA[4], accA);
        accA = fmaf(vb.x, wgtA[7], accA);
        accA = fmaf(vt.y, wgtA[2], accA);
        accA = fmaf(vm.y, wgtA[5], accA);
        accA = fmaf(vb.y, wgtA[8], accA);
        float accB = vt.y * wgtB[1];
        accB = fmaf(vm.y, wgtB[4], accB);
        accB = fmaf(vb.y, wgtB[7], accB);
        accB = fmaf(vt.x, wgtB[0], accB);
        accB = fmaf(vm.x, wgtB[3], accB);
        accB = fmaf(vb.x, wgtB[6], accB);
        float cl = vt.x * wlB0;
        cl = fmaf(vm.x, wlB1, cl);
        cl = fmaf(vb.x, wlB2, cl);
        float cr = vt.y * wrA0;
        cr = fmaf(vm.y, wrA1, cr);
        cr = fmaf(vb.y, wrA2, cr);

        float fromR = __shfl_down_sync(FULL, cl, 1);
        float fromL = __shfl_up_sync(FULL, cr, 1);

        float oA = accA + fromL + f.x;
        float oB = accB + fromR + f.y;

        float* q = ob + c * HW;
        if (st0 && st1) {
            *reinterpret_cast<float2*>(q) = make_float2(oA, oB);
        } else {
            if (st0) q[0] = oA;
            if (st1) q[1] = oB;
        }
    }
}

__global__ __launch_bounds__(NT, 28) void asfr_kernel(
    const float* __restrict__ fe,
    const float* __restrict__ fu,
    float* __restrict__ out)
{
    const int lane = threadIdx.x & 31;
    const int G    = blockIdx.x;         // one warp per block
    const int b    = G / NWPB;
    const int W    = G - b * NWPB;
    const int n0   = W * SEGO - 2;

    if (W <= 4 || W >= 1052)
        body<2>(lane, n0, b, fe, fu, out);
    else if ((n0 & 255) >= 193)
        body<1>(lane, n0, b, fe, fu, out);
    else
        body<0>(lane, n0, b, fe, fu, out);
}

extern "C" void kernel_launch(void* const* d_in, const int* in_sizes, int n_in,
                              void* d_out, int out_size)
{
    (void)in_sizes; (void)n_in; (void)out_size;
    const float* fe = (const float*)d_in[0];
    const float* fu = (const float*)d_in[1];
    float* out = (float*)d_out;

    asfr_kernel<<<NWTOT, NT>>>(fe, fu, out);   // 4232 one-warp blocks
}

// round 16
// speedup vs baseline: 1.3476x; 1.3455x over previous
#include <cuda_runtime.h>
#include <math.h>

#define CC 32
#define HH 256
#define WW 256
#define HWN (HH * WW)
#define KP 9
#define SEGO 62                 // output pixels per warp
#define NWPB 1058               // warps per batch = ceil(HWN/SEGO)
#define NBATCH 4
#define NWTOT (NWPB * NBATCH)   // 4232
#define NT 32                   // ONE warp per block
#define HW HWN

__device__ __forceinline__ float2 ld2(const float* p) {
    return *reinterpret_cast<const float2*>(p);
}

__device__ __forceinline__ void weights9(const float* __restrict__ dot,
                                         const float* __restrict__ pn2,
                                         float fn2,
                                         float* __restrict__ wgt)
{
    float rfn = rsqrtf(fmaxf(fn2, 1e-24f));
    float cs[KP], ed[KP];
    float csum = 0.0f, esum = 0.0f;
#pragma unroll
    for (int k = 0; k < KP; k++) {
        float rp = rsqrtf(fmaxf(pn2[k], 1e-24f));
        float cv = dot[k] * rp * rfn;
        float d2 = fmaxf(fmaf(-2.0f, dot[k], pn2[k] + fn2), 0.0f);
        float sd = d2 * rsqrtf(fmaxf(d2, 1e-30f));   // ~= sqrt(d2), 0-safe
        cs[k] = __expf(cv);
        csum += cs[k];
        ed[k] = __expf(-sd);
        esum += ed[k];
    }
    float ci = __fdividef(0.5f, csum);
    float ei = __fdividef(0.5f, esum);
#pragma unroll
    for (int k = 0; k < KP; k++) wgt[k] = cs[k] * ci + ed[k] * ei;
}

// MODE 0: clean interior. MODE 1: row-wrap inside window. MODE 2: y/range edge.
template<int MODE>
__device__ __forceinline__ void body(
    int lane, int n0, int b,
    const float* __restrict__ fe,
    const float* __restrict__ fu,
    float* __restrict__ out)
{
    const unsigned FULL = 0xffffffffu;
    const int nA = n0 + 2 * lane;
    const int nB = nA + 1;

    int ca = nA;
    if (MODE == 2) ca = min(max(nA, 0), HWN - 2);

    float ml = 1.0f, mr = 1.0f;
    if (MODE >= 1) {
        ml = ((ca & 255) != 0) ? 1.0f : 0.0f;
        mr = (((ca + 2) & 255) != 0) ? 1.0f : 0.0f;
    }

    float mtA = 1.0f, mtB = 1.0f, mmA = 1.0f, mmB = 1.0f, mbA = 1.0f, mbB = 1.0f;
    int ot = -WW, obo = WW;
    if (MODE == 2) {
        mmA = (nA >= 0 && nA < HWN) ? 1.0f : 0.0f;
        mmB = (nB >= 0 && nB < HWN) ? 1.0f : 0.0f;
        mtA = (nA >= WW && nA < HWN) ? 1.0f : 0.0f;
        mtB = (nB >= WW && nB < HWN) ? 1.0f : 0.0f;
        mbA = (nA >= 0 && nA + WW < HWN) ? 1.0f : 0.0f;
        mbB = (nB >= 0 && nB + WW < HWN) ? 1.0f : 0.0f;
        ot  = (nA >= WW) ? -WW : 0;
        obo = (nA + 1 + WW < HWN) ? WW : 0;
    }

    const size_t base = ((size_t)b * CC) * HW + ca;
    const float* fup = fu + base;
    const float* fep = fe + base;

    // ---- pass 1: per-column scatter accumulators ----
    float uA[3] = {0,0,0}, mA[3] = {0,0,0}, wA[3] = {0,0,0}, qA[3] = {0,0,0};
    float uB[3] = {0,0,0}, mB[3] = {0,0,0}, wB[3] = {0,0,0}, qB[3] = {0,0,0};
    float fnA = 0.0f, fnB = 0.0f;

#pragma unroll 4
    for (int c = 0; c < CC; c++) {
        const float* p = fup + c * HW;
        float2 vt = ld2(p + ot);
        float2 vm = ld2(p);
        float2 vb = ld2(p + obo);
        float2 f  = ld2(fep + c * HW);
        if (MODE == 2) {
            vt.x *= mtA; vt.y *= mtB;
            vm.x *= mmA; vm.y *= mmB;
            vb.x *= mbA; vb.y *= mbB;
            f.x  *= mmA; f.y  *= mmB;
        }

        float fl = __shfl_up_sync(FULL, f.y, 1);    // f(cA-1)
        float fr = __shfl_down_sync(FULL, f.x, 1);  // f(cB+1)
        if (MODE >= 1) { fl *= ml; fr *= mr; }

        fnA = fmaf(f.x, f.x, fnA);
        fnB = fmaf(f.y, f.y, fnB);

        float vx, vy;
        vx = vt.x; vy = vt.y;
        uA[0] = fmaf(vx, f.y, uA[0]); mA[0] = fmaf(vx, f.x, mA[0]);
        wA[0] = fmaf(vx, fl,  wA[0]); qA[0] = fmaf(vx, vx,  qA[0]);
        uB[0] = fmaf(vy, fr,  uB[0]); mB[0] = fmaf(vy, f.y, mB[0]);
        wB[0] = fmaf(vy, f.x, wB[0]); qB[0] = fmaf(vy, vy,  qB[0]);
        vx = vm.x; vy = vm.y;
        uA[1] = fmaf(vx, f.y, uA[1]); mA[1] = fmaf(vx, f.x, mA[1]);
        wA[1] = fmaf(vx, fl,  wA[1]); qA[1] = fmaf(vx, vx,  qA[1]);
        uB[1] = fmaf(vy, fr,  uB[1]); mB[1] = fmaf(vy, f.y, mB[1]);
        wB[1] = fmaf(vy, f.x, wB[1]); qB[1] = fmaf(vy, vy,  qB[1]);
        vx = vb.x; vy = vb.y;
        uA[2] = fmaf(vx, f.y, uA[2]); mA[2] = fmaf(vx, f.x, mA[2]);
        wA[2] = fmaf(vx, fl,  wA[2]); qA[2] = fmaf(vx, vx,  qA[2]);
        uB[2] = fmaf(vy, fr,  uB[2]); mB[2] = fmaf(vy, f.y, mB[2]);
        wB[2] = fmaf(vy, f.x, wB[2]); qB[2] = fmaf(vy, vy,  qB[2]);
    }

    // ---- redistribute + softmax ----
    float wgtA[KP], wgtB[KP];
    {
        float dot[KP], pn2[KP];
#pragma unroll
        for (int d = 0; d < 3; d++) {
            float a0 = __shfl_up_sync(FULL, uB[d], 1);
            float q0 = __shfl_up_sync(FULL, qB[d], 1);
            if (MODE >= 1) { a0 *= ml; q0 *= ml; }
            dot[d*3 + 0] = a0;
            dot[d*3 + 1] = mA[d];
            dot[d*3 + 2] = wB[d];
            pn2[d*3 + 0] = q0;
            pn2[d*3 + 1] = qA[d];
            pn2[d*3 + 2] = qB[d];
        }
        weights9(dot, pn2, fnA, wgtA);
    }
    {
        float dot[KP], pn2[KP];
#pragma unroll
        for (int d = 0; d < 3; d++) {
            float a2 = __shfl_down_sync(FULL, wA[d], 1);
            float q2 = __shfl_down_sync(FULL, qA[d], 1);
            if (MODE >= 1) { a2 *= mr; q2 *= mr; }
            dot[d*3 + 0] = uA[d];
            dot[d*3 + 1] = mB[d];
            dot[d*3 + 2] = a2;
            pn2[d*3 + 0] = qA[d];
            pn2[d*3 + 1] = qB[d];
            pn2[d*3 + 2] = q2;
        }
        weights9(dot, pn2, fnB, wgtB);
    }

    // pre-shuffled neighbor weights (link-masked)
    float wlB0 = __shfl_up_sync(FULL, wgtB[2], 1);
    float wlB1 = __shfl_up_sync(FULL, wgtB[5], 1);
    float wlB2 = __shfl_up_sync(FULL, wgtB[8], 1);
    float wrA0 = __shfl_down_sync(FULL, wgtA[0], 1);
    float wrA1 = __shfl_down_sync(FULL, wgtA[3], 1);
    float wrA2 = __shfl_down_sync(FULL, wgtA[6], 1);
    if (MODE >= 1) {
        wlB0 *= ml; wlB1 *= ml; wlB2 *= ml;
        wrA0 *= mr; wrA1 *= mr; wrA2 *= mr;
    }

    bool st0 = (lane >= 1);
    bool st1 = (lane <= 30);
    if (MODE == 2) {
        st0 = st0 && (nA >= 0) && (nA < HWN);
        st1 = st1 && (nB >= 0) && (nB < HWN);
    }
    float* ob = out + base;

    // ---- pass 2 (reverse channel order: last pass-1 channels are L1-hot) ----
#pragma unroll 4
    for (int ci = 0; ci < CC; ci++) {
        const int c = CC - 1 - ci;
        const float* p = fup + c * HW;
        float2 vt = ld2(p + ot);
        float2 vm = ld2(p);
        float2 vb = ld2(p + obo);
        float2 f  = ld2(fep + c * HW);
        if (MODE == 2) {
            vt.x *= mtA; vt.y *= mtB;
            vm.x *= mmA; vm.y *= mmB;
            vb.x *= mbA; vb.y *= mbB;
        }

        float accA = vt.x * wgtA[1];
        accA = fmaf(vm.x, wgtA[4], accA);
        accA = fmaf(vb.x, wgtA[7], accA);
        accA = fmaf(vt.y, wgtA[2], accA);
        accA = fmaf(vm.y, wgtA[5], accA);
        accA = fmaf(vb.y, wgtA[8], accA);
        float accB = vt.y * wgtB[1];
        accB = fmaf(vm.y, wgtB[4], accB);
        accB = fmaf(vb.y, wgtB[7], accB);
        accB = fmaf(vt.x, wgtB[0], accB);
        accB = fmaf(vm.x, wgtB[3], accB);
        accB = fmaf(vb.x, wgtB[6], accB);
        float cl = vt.x * wlB0;
        cl = fmaf(vm.x, wlB1, cl);
        cl = fmaf(vb.x, wlB2, cl);
        float cr = vt.y * wrA0;
        cr = fmaf(vm.y, wrA1, cr);
        cr = fmaf(vb.y, wrA2, cr);

        float fromR = __shfl_down_sync(FULL, cl, 1);
        float fromL = __shfl_up_sync(FULL, cr, 1);

        float oA = accA + fromL + f.x;
        float oB = accB + fromR + f.y;

        float* q = ob + c * HW;
        if (st0 && st1) {
            *reinterpret_cast<float2*>(q) = make_float2(oA, oB);
        } else {
            if (st0) q[0] = oA;
            if (st1) q[1] = oB;
        }
    }
}

__global__ __launch_bounds__(NT, 32) void asfr_kernel(
    const float* __restrict__ fe,
    const float* __restrict__ fu,
    float* __restrict__ out)
{
    const int lane = threadIdx.x & 31;
    const int G    = blockIdx.x;         // one warp per block
    const int b    = G / NWPB;
    const int W    = G - b * NWPB;
    const int n0   = W * SEGO - 2;

    if (W <= 4 || W >= 1052)
        body<2>(lane, n0, b, fe, fu, out);
    else if ((n0 & 255) >= 193)
        body<1>(lane, n0, b, fe, fu, out);
    else
        body<0>(lane, n0, b, fe, fu, out);
}

extern "C" void kernel_launch(void* const* d_in, const int* in_sizes, int n_in,
                              void* d_out, int out_size)
{
    (void)in_sizes; (void)n_in; (void)out_size;
    const float* fe = (const float*)d_in[0];
    const float* fu = (const float*)d_in[1];
    float* out = (float*)d_out;

    asfr_kernel<<<NWTOT, NT>>>(fe, fu, out);   // 4232 one-warp blocks
}